// round 1
// baseline (speedup 1.0000x reference)
#include <cuda_runtime.h>

#define Bb 16
#define Nn 512
#define Tt 24
#define Dd 64
#define Ee 64
#define Hh 64
#define SSTR 516   // S row stride in floats (64 rows x 516)

// Scratch: E1,E2 in k-major layout [B,T,E,N] (n fastest) for conflict-free tiles.
__device__ float g_e1t[Bb * Tt * Ee * Nn];
__device__ float g_e2t[Bb * Tt * Ee * Nn];

// ---------- helpers ----------
__device__ __forceinline__ unsigned long long dup2(float a) {
    unsigned long long r;
    asm("mov.b64 %0, {%1, %1};" : "=l"(r) : "f"(a));
    return r;
}
__device__ __forceinline__ void fma2(unsigned long long& c, unsigned long long a,
                                     unsigned long long b) {
    asm("fma.rn.f32x2 %0, %1, %2, %0;" : "+l"(c) : "l"(a), "l"(b));
}
__device__ __forceinline__ float2 unpk(unsigned long long v) {
    float2 r;
    asm("mov.b64 {%0, %1}, %2;" : "=f"(r.x), "=f"(r.y) : "l"(v));
    return r;
}
__device__ __forceinline__ void cp16(float* s, const float* g) {
    unsigned int sa = (unsigned int)__cvta_generic_to_shared(s);
    asm volatile("cp.async.cg.shared.global [%0], [%1], 16;" ::"r"(sa), "l"(g));
}
__device__ __forceinline__ void cp_commit() { asm volatile("cp.async.commit_group;"); }
template <int N>
__device__ __forceinline__ void cp_wait() {
    asm volatile("cp.async.wait_group %0;" ::"n"(N));
}

// ============================================================================
// Kernel A: E1 = x@W1+b1, E2 = x@W2+b2, stored k-major as [B,T,E,N].
// grid = B*T*8 (n-tiles of 64), 256 threads.
// ============================================================================
__global__ void __launch_bounds__(256, 1)
gcn_proj(const float* __restrict__ x, const float* __restrict__ W1,
         const float* __restrict__ b1, const float* __restrict__ W2,
         const float* __restrict__ b2) {
    extern __shared__ float sm[];
    float* W1s = sm;                    // 4096
    float* W2s = sm + 4096;             // 4096
    float* xs  = sm + 8192;             // 64*68
    float* et  = sm + 8192 + 64 * 68;   // 64*68
    float* b1s = et + 64 * 68;          // 64
    float* b2s = b1s + 64;              // 64

    const int tid = threadIdx.x;
    const int blk = blockIdx.x;
    const int nt = blk & 7;
    const int bt = blk >> 3;
    const int t = bt % Tt;
    const int b = bt / Tt;
    const int n0 = nt * 64;

#pragma unroll
    for (int i = 0; i < 16; i++) {
        W1s[tid + 256 * i] = W1[tid + 256 * i];
        W2s[tid + 256 * i] = W2[tid + 256 * i];
    }
    if (tid < 64) {
        b1s[tid] = b1[tid];
        b2s[tid] = b2[tid];
    }
    {
        const int r = tid >> 2, q = tid & 3;
        const float* gx = x + ((size_t)(b * Nn + n0 + r) * Tt + t) * Dd;
#pragma unroll
        for (int i = 0; i < 4; i++) {
            *(float4*)&xs[r * 68 + q * 16 + 4 * i] =
                *(const float4*)&gx[q * 16 + 4 * i];
        }
    }
    __syncthreads();

    const int r = tid >> 2;
    const int e0 = (tid & 3) * 16;
    for (int pass = 0; pass < 2; pass++) {
        const float* Wsm = pass ? W2s : W1s;
        const float* bsm = pass ? b2s : b1s;
        float* gout = (pass ? g_e2t : g_e1t) + (size_t)(b * Tt + t) * Ee * Nn + n0;

        unsigned long long acc[8];
#pragma unroll
        for (int j = 0; j < 4; j++) {
            ulonglong2 bb = *(const ulonglong2*)&bsm[e0 + 4 * j];
            acc[2 * j] = bb.x;
            acc[2 * j + 1] = bb.y;
        }
#pragma unroll 8
        for (int k = 0; k < 64; k++) {
            unsigned long long xd = dup2(xs[r * 68 + k]);
#pragma unroll
            for (int j = 0; j < 4; j++) {
                ulonglong2 wv = *(const ulonglong2*)&Wsm[k * 64 + e0 + 4 * j];
                fma2(acc[2 * j], xd, wv.x);
                fma2(acc[2 * j + 1], xd, wv.y);
            }
        }
        // store transposed tile et[e][r]
#pragma unroll
        for (int j = 0; j < 4; j++) {
            float2 p0 = unpk(acc[2 * j]), p1 = unpk(acc[2 * j + 1]);
            et[(e0 + 4 * j + 0) * 68 + r] = p0.x;
            et[(e0 + 4 * j + 1) * 68 + r] = p0.y;
            et[(e0 + 4 * j + 2) * 68 + r] = p1.x;
            et[(e0 + 4 * j + 3) * 68 + r] = p1.y;
        }
        __syncthreads();
        {
            const int e = tid >> 2, q = tid & 3;
#pragma unroll
            for (int i = 0; i < 4; i++) {
                *(float4*)&gout[(size_t)e * Nn + q * 16 + 4 * i] =
                    *(const float4*)&et[e * 68 + q * 16 + 4 * i];
            }
        }
        __syncthreads();  // et reused next pass
    }
}

// ============================================================================
// Kernel B: per (b,t,i-tile of 64): S=relu(E1 E2^T), softmax rows,
// H = A X, out = relu(H W + b).  grid = B*T*8, 256 threads.
// ============================================================================
__global__ void __launch_bounds__(256, 1)
gcn_main(const float* __restrict__ x, const float* __restrict__ W,
         const float* __restrict__ bias, float* __restrict__ out) {
    extern __shared__ float sm[];
    float* S    = sm;            // 64*516 = 33024 floats
    float* e1s  = sm + 33024;    // 4096 (reused as W in phase 4)
    float* buf0 = sm + 37120;    // 4096
    float* buf1 = sm + 41216;    // 4096
    float* Hs   = sm + 45312;    // 64*68 = 4352
    float* rinv = sm + 49664;    // 64
    float* bs   = sm + 49728;    // 64

    const int tid = threadIdx.x;
    const int blk = blockIdx.x;
    const int it = blk & 7;
    const int bt = blk >> 3;
    const int t = bt % Tt;
    const int b = bt / Tt;
    const int i0 = it * 64;

    const float* e1g = g_e1t + (size_t)(b * Tt + t) * Ee * Nn;
    const float* e2g = g_e2t + (size_t)(b * Tt + t) * Ee * Nn;
    const float* xg = x + (size_t)b * Nn * Tt * Dd + (size_t)t * Dd;  // row j: +j*Tt*Dd

    const int ridx = tid >> 4, cidx = tid & 15;
    const int r0 = ridx * 4, c0 = cidx * 4;

    // ---- phase 1 prologue: e1 tile + first two e2 tiles via cp.async ----
#pragma unroll
    for (int i = 0; i < 4; i++) {
        int ch = tid + 256 * i, row = ch >> 4, col = (ch & 15) * 4;
        cp16(&e1s[row * 64 + col], &e1g[row * Nn + i0 + col]);
    }
#pragma unroll
    for (int i = 0; i < 4; i++) {
        int ch = tid + 256 * i, row = ch >> 4, col = (ch & 15) * 4;
        cp16(&buf0[row * 64 + col], &e2g[row * Nn + col]);
    }
    cp_commit();
#pragma unroll
    for (int i = 0; i < 4; i++) {
        int ch = tid + 256 * i, row = ch >> 4, col = (ch & 15) * 4;
        cp16(&buf1[row * 64 + col], &e2g[row * Nn + 64 + col]);
    }
    cp_commit();
    cp_wait<1>();
    __syncthreads();

    // ---- phase 1: S = relu(E1 E2^T), tiled 64x64, f32x2 FMAs ----
    for (int jt = 0; jt < 8; jt++) {
        const float* cur = (jt & 1) ? buf1 : buf0;
        unsigned long long acc[4][2];
#pragma unroll
        for (int u = 0; u < 4; u++) { acc[u][0] = 0ull; acc[u][1] = 0ull; }
#pragma unroll 8
        for (int k = 0; k < 64; k++) {
            ulonglong2 bv = *(const ulonglong2*)&cur[k * 64 + c0];
#pragma unroll
            for (int u = 0; u < 4; u++) {
                unsigned long long a = dup2(e1s[k * 64 + r0 + u]);
                fma2(acc[u][0], a, bv.x);
                fma2(acc[u][1], a, bv.y);
            }
        }
        const int j0 = jt * 64;
#pragma unroll
        for (int u = 0; u < 4; u++) {
            float2 p0 = unpk(acc[u][0]), p1 = unpk(acc[u][1]);
            *(float4*)&S[(r0 + u) * SSTR + j0 + c0] =
                make_float4(fmaxf(p0.x, 0.f), fmaxf(p0.y, 0.f),
                            fmaxf(p1.x, 0.f), fmaxf(p1.y, 0.f));
        }
        __syncthreads();  // all reads of cur done before refill
        if (jt + 2 < 8) {
            const int jn = (jt + 2) * 64;
            float* nb = (jt & 1) ? buf1 : buf0;
#pragma unroll
            for (int i = 0; i < 4; i++) {
                int ch = tid + 256 * i, row = ch >> 4, col = (ch & 15) * 4;
                cp16(&nb[row * 64 + col], &e2g[row * Nn + jn + col]);
            }
            cp_commit();
            cp_wait<1>();
            __syncthreads();
        } else if (jt + 1 < 8) {
            cp_wait<0>();
            __syncthreads();
        }
    }

    // ---- phase 3 prologue issued early: x tiles 0/1, W, bias (overlap softmax) ----
#pragma unroll
    for (int i = 0; i < 4; i++) {
        int ch = tid + 256 * i, row = ch >> 4, col = (ch & 15) * 4;
        cp16(&buf0[row * 64 + col], &xg[(size_t)row * (Tt * Dd) + col]);
    }
#pragma unroll
    for (int i = 0; i < 4; i++) {
        int ch = tid + 256 * i;
        cp16(&e1s[ch * 4], &W[ch * 4]);  // e1s free -> holds W now
    }
    if (tid < 16) cp16(&bs[tid * 4], &bias[tid * 4]);
    cp_commit();
#pragma unroll
    for (int i = 0; i < 4; i++) {
        int ch = tid + 256 * i, row = ch >> 4, col = (ch & 15) * 4;
        cp16(&buf1[row * 64 + col], &xg[(size_t)(row + 64) * (Tt * Dd) + col]);
    }
    cp_commit();

    // ---- phase 2: softmax over rows of S (keep P=exp unnormalized; 1/sum saved) ----
    {
        const int w = tid >> 5, l = tid & 31;
#pragma unroll
        for (int rr = 0; rr < 8; rr++) {
            float* row = &S[(w * 8 + rr) * SSTR];
            float4 v[4];
#pragma unroll
            for (int p = 0; p < 4; p++) v[p] = *(float4*)&row[4 * l + 128 * p];
            float m = 0.f;  // relu'ed scores are >= 0
#pragma unroll
            for (int p = 0; p < 4; p++)
                m = fmaxf(m, fmaxf(fmaxf(v[p].x, v[p].y), fmaxf(v[p].z, v[p].w)));
#pragma unroll
            for (int o = 16; o > 0; o >>= 1)
                m = fmaxf(m, __shfl_xor_sync(0xffffffffu, m, o));
            float s = 0.f;
#pragma unroll
            for (int p = 0; p < 4; p++) {
                v[p].x = __expf(v[p].x - m);
                v[p].y = __expf(v[p].y - m);
                v[p].z = __expf(v[p].z - m);
                v[p].w = __expf(v[p].w - m);
                s += (v[p].x + v[p].y) + (v[p].z + v[p].w);
                *(float4*)&row[4 * l + 128 * p] = v[p];
            }
#pragma unroll
            for (int o = 16; o > 0; o >>= 1) s += __shfl_xor_sync(0xffffffffu, s, o);
            if (l == 0) rinv[w * 8 + rr] = 1.f / s;
        }
    }
    __syncthreads();

    // ---- phase 3: H = P X (scaled by 1/rowsum at epilogue) ----
    cp_wait<1>();
    __syncthreads();
    unsigned long long acc3[4][2];
#pragma unroll
    for (int u = 0; u < 4; u++) { acc3[u][0] = 0ull; acc3[u][1] = 0ull; }
    for (int jt = 0; jt < 8; jt++) {
        const float* cur = (jt & 1) ? buf1 : buf0;
        const int j0 = jt * 64;
#pragma unroll 8
        for (int jj = 0; jj < 64; jj++) {
            ulonglong2 xv = *(const ulonglong2*)&cur[jj * 64 + c0];
#pragma unroll
            for (int u = 0; u < 4; u++) {
                unsigned long long a = dup2(S[(r0 + u) * SSTR + j0 + jj]);
                fma2(acc3[u][0], a, xv.x);
                fma2(acc3[u][1], a, xv.y);
            }
        }
        __syncthreads();
        if (jt + 2 < 8) {
            const int jn = (jt + 2) * 64;
            float* nb = (jt & 1) ? buf1 : buf0;
#pragma unroll
            for (int i = 0; i < 4; i++) {
                int ch = tid + 256 * i, row = ch >> 4, col = (ch & 15) * 4;
                cp16(&nb[row * 64 + col], &xg[(size_t)(row + jn) * (Tt * Dd) + col]);
            }
            cp_commit();
            cp_wait<1>();
            __syncthreads();
        } else if (jt + 1 < 8) {
            cp_wait<0>();
            __syncthreads();
        }
    }
#pragma unroll
    for (int u = 0; u < 4; u++) {
        float inv = rinv[r0 + u];
        float2 p0 = unpk(acc3[u][0]), p1 = unpk(acc3[u][1]);
        *(float4*)&Hs[(r0 + u) * 68 + c0] =
            make_float4(p0.x * inv, p0.y * inv, p1.x * inv, p1.y * inv);
    }
    __syncthreads();

    // ---- phase 4: out = relu(H W + b) ----
    const float* Wsm = e1s;  // W loaded here in phase-3 prologue
    unsigned long long acc4[4][2];
#pragma unroll
    for (int u = 0; u < 4; u++) { acc4[u][0] = 0ull; acc4[u][1] = 0ull; }
#pragma unroll 8
    for (int d = 0; d < 64; d++) {
        ulonglong2 wv = *(const ulonglong2*)&Wsm[d * 64 + c0];
#pragma unroll
        for (int u = 0; u < 4; u++) {
            unsigned long long a = dup2(Hs[(r0 + u) * 68 + d]);
            fma2(acc4[u][0], a, wv.x);
            fma2(acc4[u][1], a, wv.y);
        }
    }
    const float4 bb = *(const float4*)&bs[c0];
#pragma unroll
    for (int u = 0; u < 4; u++) {
        float2 p0 = unpk(acc4[u][0]), p1 = unpk(acc4[u][1]);
        float4 o = make_float4(fmaxf(p0.x + bb.x, 0.f), fmaxf(p0.y + bb.y, 0.f),
                               fmaxf(p1.x + bb.z, 0.f), fmaxf(p1.y + bb.w, 0.f));
        *(float4*)&out[((size_t)(b * Nn + i0 + r0 + u) * Tt + t) * Hh + c0] = o;
    }
}

// ============================================================================
extern "C" void kernel_launch(void* const* d_in, const int* in_sizes, int n_in,
                              void* d_out, int out_size) {
    const float* x  = (const float*)d_in[0];
    const float* W1 = (const float*)d_in[1];
    const float* b1 = (const float*)d_in[2];
    const float* W2 = (const float*)d_in[3];
    const float* b2 = (const float*)d_in[4];
    const float* W  = (const float*)d_in[5];
    const float* bias = (const float*)d_in[6];
    float* out = (float*)d_out;

    const int smemA = (4096 + 4096 + 64 * 68 + 64 * 68 + 128) * 4;   // 68,608 B
    const int smemB = (33024 + 4096 * 3 + 64 * 68 + 128) * 4;        // 199,168 B
    cudaFuncSetAttribute(gcn_proj, cudaFuncAttributeMaxDynamicSharedMemorySize, smemA);
    cudaFuncSetAttribute(gcn_main, cudaFuncAttributeMaxDynamicSharedMemorySize, smemB);

    const int grid = Bb * Tt * (Nn / 64);  // 3072
    gcn_proj<<<grid, 256, smemA>>>(x, W1, b1, W2, b2);
    gcn_main<<<grid, 256, smemB>>>(x, W, bias, out);
}

// round 2
// speedup vs baseline: 1.3196x; 1.3196x over previous
#include <cuda_runtime.h>

#define Bb 16
#define Nn 512
#define Tt 24
#define Dd 64
#define Ee 64
#define Hh 64

// E2 scratch, k-major [B,T,E,N]
__device__ float g_e2t[Bb * Tt * Ee * Nn];

typedef unsigned long long ull;

// ---------- helpers ----------
__device__ __forceinline__ ull dup2(float a) {
    ull r;
    asm("mov.b64 %0, {%1, %1};" : "=l"(r) : "f"(a));
    return r;
}
__device__ __forceinline__ void fma2(ull& c, ull a, ull b) {
    asm("fma.rn.f32x2 %0, %1, %2, %0;" : "+l"(c) : "l"(a), "l"(b));
}
__device__ __forceinline__ float2 unpk(ull v) {
    float2 r;
    asm("mov.b64 {%0, %1}, %2;" : "=f"(r.x), "=f"(r.y) : "l"(v));
    return r;
}
__device__ __forceinline__ void cp16(float* s, const float* g) {
    unsigned int sa = (unsigned int)__cvta_generic_to_shared(s);
    asm volatile("cp.async.cg.shared.global [%0], [%1], 16;" ::"r"(sa), "l"(g));
}
__device__ __forceinline__ void cp_commit() { asm volatile("cp.async.commit_group;"); }
template <int N>
__device__ __forceinline__ void cp_wait() {
    asm volatile("cp.async.wait_group %0;" ::"n"(N));
}

// ============================================================================
// Kernel P: E2^T = (x@W2+b2)^T stored k-major [B,T,E,N].
// grid = B*T*2 (n-halves of 256), 256 threads, 4 row-tiles per block.
// ============================================================================
__global__ void __launch_bounds__(256, 2)
gcn_proj(const float* __restrict__ x, const float* __restrict__ W2,
         const float* __restrict__ b2) {
    extern __shared__ float sm[];
    float* W2s = sm;          // 4096
    float* xs0 = sm + 4096;   // 64*68
    float* xs1 = sm + 8448;   // 64*68
    float* et  = sm + 12800;  // 64*68
    float* b2s = sm + 17152;  // 64

    const int tid = threadIdx.x;
    const int blk = blockIdx.x;
    const int half = blk & 1;
    const int bt = blk >> 1;
    const int t = bt % Tt, b = bt / Tt;
    const int nbase = half * 256;
    const float* xg = x + ((size_t)b * Nn * Tt + t) * Dd;

    // prologue: x tiles 0,1 via cp.async
#pragma unroll
    for (int i = 0; i < 4; i++) {
        int ch = tid + 256 * i, row = ch >> 4, col = (ch & 15) * 4;
        cp16(&xs0[row * 68 + col], &xg[(size_t)(nbase + row) * (Tt * Dd) + col]);
    }
    cp_commit();
#pragma unroll
    for (int i = 0; i < 4; i++) {
        int ch = tid + 256 * i, row = ch >> 4, col = (ch & 15) * 4;
        cp16(&xs1[row * 68 + col], &xg[(size_t)(nbase + 64 + row) * (Tt * Dd) + col]);
    }
    cp_commit();
#pragma unroll
    for (int i = 0; i < 16; i++) W2s[tid + 256 * i] = W2[tid + 256 * i];
    if (tid < 64) b2s[tid] = b2[tid];

    const int r = tid >> 2;
    const int e0 = (tid & 3) * 16;

    for (int tl = 0; tl < 4; tl++) {
        if (tl < 3) cp_wait<1>(); else cp_wait<0>();
        __syncthreads();
        const float* xs = (tl & 1) ? xs1 : xs0;

        ull acc[8];
#pragma unroll
        for (int j = 0; j < 4; j++) {
            ulonglong2 bb = *(const ulonglong2*)&b2s[e0 + 4 * j];
            acc[2 * j] = bb.x; acc[2 * j + 1] = bb.y;
        }
#pragma unroll 8
        for (int k = 0; k < 64; k++) {
            ull xd = dup2(xs[r * 68 + k]);
#pragma unroll
            for (int j = 0; j < 4; j++) {
                ulonglong2 wv = *(const ulonglong2*)&W2s[k * 64 + e0 + 4 * j];
                fma2(acc[2 * j], xd, wv.x);
                fma2(acc[2 * j + 1], xd, wv.y);
            }
        }
#pragma unroll
        for (int j = 0; j < 4; j++) {
            float2 p0 = unpk(acc[2 * j]), p1 = unpk(acc[2 * j + 1]);
            et[(e0 + 4 * j + 0) * 68 + r] = p0.x;
            et[(e0 + 4 * j + 1) * 68 + r] = p0.y;
            et[(e0 + 4 * j + 2) * 68 + r] = p1.x;
            et[(e0 + 4 * j + 3) * 68 + r] = p1.y;
        }
        __syncthreads();
        {
            float* gout = g_e2t + (size_t)(b * Tt + t) * Ee * Nn + nbase + tl * 64;
            const int e = tid >> 2, q = tid & 3;
#pragma unroll
            for (int i = 0; i < 4; i++)
                *(float4*)&gout[(size_t)e * Nn + q * 16 + 4 * i] =
                    *(const float4*)&et[e * 68 + q * 16 + 4 * i];
        }
        __syncthreads();
        if (tl + 2 < 4) {
            float* xd_ = (tl & 1) ? xs1 : xs0;
#pragma unroll
            for (int i = 0; i < 4; i++) {
                int ch = tid + 256 * i, row = ch >> 4, col = (ch & 15) * 4;
                cp16(&xd_[row * 68 + col],
                     &xg[(size_t)(nbase + (tl + 2) * 64 + row) * (Tt * Dd) + col]);
            }
            cp_commit();
        }
    }
}

// ============================================================================
// Kernel M: per (b,t,i-tile): E1=x_i@W1+b1; stream j-tiles:
//   S=E1 E2^T, P=exp(relu(S)) (max-free), H += P X; then out=relu(H/rs @ W + b)
// grid = B*T*8, 256 threads, 2 CTAs/SM.
// ============================================================================
__global__ void __launch_bounds__(256, 2)
gcn_main(const float* __restrict__ x, const float* __restrict__ W1,
         const float* __restrict__ b1, const float* __restrict__ W,
         const float* __restrict__ bias, float* __restrict__ out) {
    extern __shared__ float sm[];
    float* e1s = sm;           // 4352  [e*68 + r] (E1 transposed)
    float* xb0 = sm + 4352;    // 4096
    float* xb1 = sm + 8448;    // 4096
    float* eb0 = sm + 12544;   // 4096 (also W in phase 4)
    float* eb1 = sm + 16640;   // 4096
    float* Pt  = sm + 20736;   // 6144 swizzled [j] rows stride 96 (also W1 staging, H^T)
    float* bs1 = sm + 26880;   // 64
    float* bsO = sm + 26944;   // 64   (total 27008 floats)

    const int tid = threadIdx.x;
    const int blk = blockIdx.x;
    const int it = blk & 7, bt = blk >> 3;
    const int t = bt % Tt, b = bt / Tt;
    const int i0 = it * 64;

    const float* e2g = g_e2t + (size_t)(b * Tt + t) * Ee * Nn;
    const float* xg = x + ((size_t)b * Nn * Tt + t) * Dd;

    const int ridx = tid >> 4, cidx = tid & 15;
    const int r0 = ridx * 4, c0 = cidx * 4;

    // G1: x_i -> xb0, W1 -> Pt(stride 64), biases
#pragma unroll
    for (int i = 0; i < 4; i++) {
        int ch = tid + 256 * i, row = ch >> 4, col = (ch & 15) * 4;
        cp16(&xb0[row * 64 + col], &xg[(size_t)(i0 + row) * (Tt * Dd) + col]);
    }
#pragma unroll
    for (int i = 0; i < 4; i++) {
        int ch = tid + 256 * i;
        cp16(&Pt[ch * 4], &W1[ch * 4]);
    }
    if (tid < 16) cp16(&bs1[tid * 4], &b1[tid * 4]);
    else if (tid < 32) cp16(&bsO[(tid - 16) * 4], &bias[(tid - 16) * 4]);
    cp_commit();
    // G2: e2_0 -> eb0, x_0 -> xb1
#pragma unroll
    for (int i = 0; i < 4; i++) {
        int ch = tid + 256 * i, row = ch >> 4, col = (ch & 15) * 4;
        cp16(&eb0[row * 64 + col], &e2g[row * Nn + col]);
        cp16(&xb1[row * 64 + col], &xg[(size_t)row * (Tt * Dd) + col]);
    }
    cp_commit();
    cp_wait<1>();
    __syncthreads();

    // ---- E1 = x_i @ W1 + b1  -> e1s transposed (stride 68) ----
    {
        ull a1[4][2];
        ulonglong2 bb = *(const ulonglong2*)&bs1[c0];
#pragma unroll
        for (int u = 0; u < 4; u++) { a1[u][0] = bb.x; a1[u][1] = bb.y; }
#pragma unroll 8
        for (int d = 0; d < 64; d++) {
            ulonglong2 wv = *(const ulonglong2*)&Pt[d * 64 + c0];
#pragma unroll
            for (int u = 0; u < 4; u++) {
                ull ad = dup2(xb0[(r0 + u) * 64 + d]);
                fma2(a1[u][0], ad, wv.x);
                fma2(a1[u][1], ad, wv.y);
            }
        }
#pragma unroll
        for (int u = 0; u < 4; u++) {
            float2 p0 = unpk(a1[u][0]), p1 = unpk(a1[u][1]);
            e1s[(c0 + 0) * 68 + r0 + u] = p0.x;
            e1s[(c0 + 1) * 68 + r0 + u] = p0.y;
            e1s[(c0 + 2) * 68 + r0 + u] = p1.x;
            e1s[(c0 + 3) * 68 + r0 + u] = p1.y;
        }
    }
    __syncthreads();

    float rsp[4] = {0.f, 0.f, 0.f, 0.f};
    ull acc3[4][2];
#pragma unroll
    for (int u = 0; u < 4; u++) { acc3[u][0] = 0ull; acc3[u][1] = 0ull; }

    const int pb = c0 * 96 + (cidx & 7) * 4 + r0;  // swizzled transposed-store base

    for (int jt = 0; jt < 8; jt++) {
        // prefetch next tiles (or W on last iter)
        if (jt < 7) {
            const float* e2s_ = e2g + (jt + 1) * 64;
            float* ed = ((jt + 1) & 1) ? eb1 : eb0;
            float* xd = (jt & 1) ? xb1 : xb0;
#pragma unroll
            for (int i = 0; i < 4; i++) {
                int ch = tid + 256 * i, row = ch >> 4, col = (ch & 15) * 4;
                cp16(&ed[row * 64 + col], &e2s_[row * Nn + col]);
                cp16(&xd[row * 64 + col],
                     &xg[(size_t)((jt + 1) * 64 + row) * (Tt * Dd) + col]);
            }
            cp_commit();
        } else {
#pragma unroll
            for (int i = 0; i < 4; i++) {
                int ch = tid + 256 * i;
                cp16(&eb0[ch * 4], &W[ch * 4]);
            }
            cp_commit();
        }
        cp_wait<1>();
        __syncthreads();

        // ---- GEMM1: S-tile = E1 E2^T ----
        const float* ec = (jt & 1) ? eb1 : eb0;
        ull acc[4][2];
#pragma unroll
        for (int u = 0; u < 4; u++) { acc[u][0] = 0ull; acc[u][1] = 0ull; }
#pragma unroll 8
        for (int e = 0; e < 64; e++) {
            float4 a4 = *(const float4*)&e1s[e * 68 + r0];
            ulonglong2 bv = *(const ulonglong2*)&ec[e * 64 + c0];
            ull d0 = dup2(a4.x), d1 = dup2(a4.y), d2 = dup2(a4.z), d3 = dup2(a4.w);
            fma2(acc[0][0], d0, bv.x); fma2(acc[0][1], d0, bv.y);
            fma2(acc[1][0], d1, bv.x); fma2(acc[1][1], d1, bv.y);
            fma2(acc[2][0], d2, bv.x); fma2(acc[2][1], d2, bv.y);
            fma2(acc[3][0], d3, bv.x); fma2(acc[3][1], d3, bv.y);
        }
        // ---- exp(relu(s)) (max-free), partial row sums, transposed P store ----
        float pv[4][4];
#pragma unroll
        for (int u = 0; u < 4; u++) {
            float2 p0 = unpk(acc[u][0]), p1 = unpk(acc[u][1]);
            pv[u][0] = __expf(fminf(fmaxf(p0.x, 0.f), 80.f));
            pv[u][1] = __expf(fminf(fmaxf(p0.y, 0.f), 80.f));
            pv[u][2] = __expf(fminf(fmaxf(p1.x, 0.f), 80.f));
            pv[u][3] = __expf(fminf(fmaxf(p1.y, 0.f), 80.f));
            rsp[u] += (pv[u][0] + pv[u][1]) + (pv[u][2] + pv[u][3]);
        }
#pragma unroll
        for (int v = 0; v < 4; v++)
            *(float4*)&Pt[pb + v * 96] =
                make_float4(pv[0][v], pv[1][v], pv[2][v], pv[3][v]);
        __syncthreads();

        // ---- GEMM2: H += P X ----
        const float* xc = (jt & 1) ? xb0 : xb1;
#pragma unroll 8
        for (int jj = 0; jj < 64; jj++) {
            float4 a4 = *(const float4*)&Pt[jj * 96 + ((jj >> 2) & 7) * 4 + r0];
            ulonglong2 xv = *(const ulonglong2*)&xc[jj * 64 + c0];
            ull d0 = dup2(a4.x), d1 = dup2(a4.y), d2 = dup2(a4.z), d3 = dup2(a4.w);
            fma2(acc3[0][0], d0, xv.x); fma2(acc3[0][1], d0, xv.y);
            fma2(acc3[1][0], d1, xv.x); fma2(acc3[1][1], d1, xv.y);
            fma2(acc3[2][0], d2, xv.x); fma2(acc3[2][1], d2, xv.y);
            fma2(acc3[3][0], d3, xv.x); fma2(acc3[3][1], d3, xv.y);
        }
        __syncthreads();
    }

    // ---- finalize row sums (16-lane butterfly; lanes share rows) ----
#pragma unroll
    for (int u = 0; u < 4; u++) {
#pragma unroll
        for (int o = 1; o < 16; o <<= 1)
            rsp[u] += __shfl_xor_sync(0xffffffffu, rsp[u], o);
        rsp[u] = 1.f / rsp[u];
    }
    // ---- H normalized -> Pt transposed ----
    {
        float hv[4][4];
#pragma unroll
        for (int u = 0; u < 4; u++) {
            float2 p0 = unpk(acc3[u][0]), p1 = unpk(acc3[u][1]);
            hv[u][0] = p0.x * rsp[u]; hv[u][1] = p0.y * rsp[u];
            hv[u][2] = p1.x * rsp[u]; hv[u][3] = p1.y * rsp[u];
        }
#pragma unroll
        for (int v = 0; v < 4; v++)
            *(float4*)&Pt[pb + v * 96] =
                make_float4(hv[0][v], hv[1][v], hv[2][v], hv[3][v]);
    }
    cp_wait<0>();
    __syncthreads();

    // ---- phase 4: out = relu(H W + b) ----
    ull a4c[4][2];
    {
        ulonglong2 bo = *(const ulonglong2*)&bsO[c0];
#pragma unroll
        for (int u = 0; u < 4; u++) { a4c[u][0] = bo.x; a4c[u][1] = bo.y; }
    }
#pragma unroll 8
    for (int d = 0; d < 64; d++) {
        float4 a4 = *(const float4*)&Pt[d * 96 + ((d >> 2) & 7) * 4 + r0];
        ulonglong2 wv = *(const ulonglong2*)&eb0[d * 64 + c0];
        ull d0 = dup2(a4.x), d1 = dup2(a4.y), d2 = dup2(a4.z), d3 = dup2(a4.w);
        fma2(a4c[0][0], d0, wv.x); fma2(a4c[0][1], d0, wv.y);
        fma2(a4c[1][0], d1, wv.x); fma2(a4c[1][1], d1, wv.y);
        fma2(a4c[2][0], d2, wv.x); fma2(a4c[2][1], d2, wv.y);
        fma2(a4c[3][0], d3, wv.x); fma2(a4c[3][1], d3, wv.y);
    }
#pragma unroll
    for (int u = 0; u < 4; u++) {
        float2 p0 = unpk(a4c[u][0]), p1 = unpk(a4c[u][1]);
        float4 o = make_float4(fmaxf(p0.x, 0.f), fmaxf(p0.y, 0.f),
                               fmaxf(p1.x, 0.f), fmaxf(p1.y, 0.f));
        *(float4*)&out[((size_t)(b * Nn + i0 + r0 + u) * Tt + t) * Hh + c0] = o;
    }
}

// ============================================================================
extern "C" void kernel_launch(void* const* d_in, const int* in_sizes, int n_in,
                              void* d_out, int out_size) {
    const float* x  = (const float*)d_in[0];
    const float* W1 = (const float*)d_in[1];
    const float* b1 = (const float*)d_in[2];
    const float* W2 = (const float*)d_in[3];
    const float* b2 = (const float*)d_in[4];
    const float* W  = (const float*)d_in[5];
    const float* bias = (const float*)d_in[6];
    float* out = (float*)d_out;

    const int smemP = 17216 * 4;  // 68,864 B
    const int smemM = 27008 * 4;  // 108,032 B
    cudaFuncSetAttribute(gcn_proj, cudaFuncAttributeMaxDynamicSharedMemorySize, smemP);
    cudaFuncSetAttribute(gcn_main, cudaFuncAttributeMaxDynamicSharedMemorySize, smemM);

    gcn_proj<<<Bb * Tt * 2, 256, smemP>>>(x, W2, b2);
    gcn_main<<<Bb * Tt * 8, 256, smemM>>>(x, W1, b1, W, bias, out);
}